// round 3
// baseline (speedup 1.0000x reference)
#include <cuda_runtime.h>
#include <math.h>

// Problem constants (match reference hyperparameters)
#define BB 8
#define HH 320
#define WW 1024
#define NPIX (BB * HH * WW)          // 2,621,440 per plane
#define NOFF 105                      // (2*7+1)*(2*3+1) search offsets
#define RR 20                         // sense radius
#define KDIM 41
#define KSZ (KDIM * KDIM)             // 1681
#define TILE 32
#define TX (WW / TILE)                // 32
#define TY (HH / TILE)                // 10
#define NBINS (BB * TY * TX)          // 2560
#define CAP 256                       // >= 144 provable max points/tile

// Scratch (device globals; no allocation allowed)
__device__ float4 g_pts[NBINS * CAP];
__device__ int    g_cnt[NBINS];
__device__ float  g_K[KSZ];

// ---------------------------------------------------------------------------
// K0: zero bin counters, build 41x41 weight table from cxx/cyy
// ---------------------------------------------------------------------------
__global__ void bn_init(const float* __restrict__ cxx, const float* __restrict__ cyy) {
    int i = blockIdx.x * blockDim.x + threadIdx.x;
    if (i < NBINS) g_cnt[i] = 0;
    if (i < KSZ) {
        float cx = cxx[i], cy = cyy[i];
        float d = sqrtf(cx * cx + cy * cy);
        float w = 0.7f * expf(-d * 1.9f / 24.0f);
        g_K[((int)cy + RR) * KDIM + ((int)cx + RR)] = w;
    }
}

// ---------------------------------------------------------------------------
// K1: sparsify src, ordered window match in dst, write 4 per-pixel planes,
//     append found points to per-tile bins.
// ---------------------------------------------------------------------------
__global__ void bn_match(const float* __restrict__ src,
                         const float* __restrict__ dst,
                         const float* __restrict__ offx,
                         const float* __restrict__ offy,
                         float* __restrict__ out) {
    int idx = blockIdx.x * blockDim.x + threadIdx.x;
    if (idx >= NPIX) return;
    int x = idx & (WW - 1);
    int y = (idx / WW) % HH;
    int b = idx / (WW * HH);
    const float* S = src + (size_t)b * HH * WW;
    const float* D = dst + (size_t)b * HH * WW;

    float m = 0.0f, vx = 0.0f, vy = 0.0f;

    if (S[y * WW + x] > 0.5f) {
        // sparsity: suppressed if any src pixel at a raster-preceding offset
        // within radius 2 is active.
        bool kept = true;
        #pragma unroll
        for (int dy = -2; dy <= 0; ++dy) {
            int yn = y + dy;
            if (yn < 0) continue;
            int dxmax = (dy == 0) ? -1 : 2;
            #pragma unroll
            for (int dx = -2; dx <= 2; ++dx) {
                if (dx > dxmax) break;
                int xn = x + dx;
                if (xn < 0 || xn >= WW) continue;
                if (S[yn * WW + xn] > 0.5f) { kept = false; }
            }
            if (!kept) break;
        }
        if (kept) {
            // ordered (distance-sorted) search: first hit wins
            for (int k = 0; k < NOFF; ++k) {
                float fx = __ldg(offx + k), fy = __ldg(offy + k);
                int X = x + (int)fx, Y = y + (int)fy;
                if (X < 0 || X >= WW || Y < 0 || Y >= HH) continue;
                if (__ldg(D + Y * WW + X) > 0.5f) {
                    m = 1.0f; vx = fx; vy = fy;
                    break;
                }
            }
        }
    }

    float xf = (float)x, yf = (float)y;
    out[2 * NPIX + idx] = xf * m;          // orgpts_x
    out[3 * NPIX + idx] = yf * m;          // orgpts_y
    out[4 * NPIX + idx] = (xf + vx) * m;   // correspts_x
    out[5 * NPIX + idx] = (yf + vy) * m;   // correspts_y

    if (m > 0.0f) {
        int bin = (b * TY + (y >> 5)) * TX + (x >> 5);
        int pos = atomicAdd(&g_cnt[bin], 1);
        if (pos < CAP) g_pts[bin * CAP + pos] = make_float4(xf, yf, vx, vy);
    }
}

// ---------------------------------------------------------------------------
// K2: sparse gather "conv". One block = one 32x32 tile; each thread owns the
//     4 pixels (lx, ly0 + 8*i). Iterate points of the 3x3 tile neighborhood.
// ---------------------------------------------------------------------------
__global__ void __launch_bounds__(256) bn_splat(float* __restrict__ out) {
    __shared__ float sK[KSZ];
    int t = threadIdx.x;
    for (int i = t; i < KSZ; i += 256) sK[i] = g_K[i];
    __syncthreads();

    int blk = blockIdx.x;
    int tx = blk % TX;
    int ty = (blk / TX) % TY;
    int b  = blk / (TX * TY);

    int lx = t & 31;
    int ly0 = t >> 5;                 // 0..7
    int gx = (tx << 5) + lx;
    int gyb = (ty << 5) + ly0;        // pixel i is at row gyb + 8*i

    float a0[4] = {0, 0, 0, 0};
    float a1[4] = {0, 0, 0, 0};
    float a2[4] = {0, 0, 0, 0};

    for (int nty = ty - 1; nty <= ty + 1; ++nty) {
        if (nty < 0 || nty >= TY) continue;
        for (int ntx = tx - 1; ntx <= tx + 1; ++ntx) {
            if (ntx < 0 || ntx >= TX) continue;
            int bin = (b * TY + nty) * TX + ntx;
            int cnt = g_cnt[bin];
            if (cnt > CAP) cnt = CAP;
            const float4* P = g_pts + (size_t)bin * CAP;
            for (int j = 0; j < cnt; ++j) {
                float4 p = __ldg(P + j);   // uniform across block -> broadcast
                int dx = (int)p.x - gx;
                if (dx < -RR || dx > RR) continue;
                int dyb = (int)p.y - gyb;  // dy for i=0; decreases by 8 per i
                int kbase = dx + RR;
                #pragma unroll
                for (int i = 0; i < 4; ++i) {
                    int dy = dyb - (i << 3);
                    if (dy >= -RR && dy <= RR) {
                        float w = sK[(dy + RR) * KDIM + kbase];
                        a0[i] += w;
                        a1[i] += w * p.z;
                        a2[i] += w * p.w;
                    }
                }
            }
        }
    }

    #pragma unroll
    for (int i = 0; i < 4; ++i) {
        int gy = gyb + (i << 3);
        int idx = (b * HH + gy) * WW + gx;
        float den = a0[i] + 1.6f;           // ALPHA_PAD
        out[idx]        = (float)gx + a1[i] / den;   // morphedx
        out[NPIX + idx] = (float)gy + a2[i] / den;   // morphedy
    }
}

// ---------------------------------------------------------------------------
extern "C" void kernel_launch(void* const* d_in, const int* in_sizes, int n_in,
                              void* d_out, int out_size) {
    const float* src  = (const float*)d_in[0];   // binMapsrc [8,1,320,1024]
    const float* dst  = (const float*)d_in[1];   // binMapdst
    const float* offx = (const float*)d_in[2];   // xx [105]
    const float* offy = (const float*)d_in[3];   // yy [105]
    // d_in[4], d_in[5] = sxx, syy (constant meshgrid; logic hardcoded)
    const float* cxx  = (const float*)d_in[6];   // [1681]
    const float* cyy  = (const float*)d_in[7];   // [1681]
    float* out = (float*)d_out;                  // 6 planes of [8,320,1024]

    bn_init<<<3, 1024>>>(cxx, cyy);
    bn_match<<<(NPIX + 255) / 256, 256>>>(src, dst, offx, offy, out);
    bn_splat<<<NBINS, 256>>>(out);
}

// round 6
// speedup vs baseline: 1.2779x; 1.2779x over previous
#include <cuda_runtime.h>
#include <math.h>

// Problem constants (match reference hyperparameters)
#define BB 8
#define HH 320
#define WW 1024
#define NPIX (BB * HH * WW)          // 2,621,440 per plane
#define NOFF 105                      // (2*7+1)*(2*3+1) search offsets
#define RR 20                         // sense radius
#define KDIM 41
#define KSZ (KDIM * KDIM)             // 1681
#define TILE 32
#define TX (WW / TILE)                // 32
#define TY (HH / TILE)                // 10
#define NBINS (BB * TY * TX)          // 2560
#define CAP 256                       // >= 144 provable max points/tile
#define SCAP 1024                     // provable max points in 96x96 (spacing>=3)

// Scratch (device globals; no allocation allowed)
__device__ float4 g_pts[NBINS * CAP];
__device__ int    g_cnt[NBINS];
__device__ float  g_K[KSZ];
__device__ int2   g_off[NOFF];        // packed search offsets (dx, dy)

// ---------------------------------------------------------------------------
// K0: zero bin counters, build 41x41 weight table, pack search offsets
// ---------------------------------------------------------------------------
__global__ void bn_init(const float* __restrict__ cxx, const float* __restrict__ cyy,
                        const float* __restrict__ offx, const float* __restrict__ offy) {
    int i = blockIdx.x * blockDim.x + threadIdx.x;
    if (i < NBINS) g_cnt[i] = 0;
    if (i < KSZ) {
        float cx = cxx[i], cy = cyy[i];
        float d = sqrtf(cx * cx + cy * cy);
        float w = 0.7f * expf(-d * 1.9f / 24.0f);
        g_K[((int)cy + RR) * KDIM + ((int)cx + RR)] = w;
    }
    if (i < NOFF) g_off[i] = make_int2((int)offx[i], (int)offy[i]);
}

// ---------------------------------------------------------------------------
// K1: sparsify src, ordered window match in dst, write 4 per-pixel planes
//     (vectorized: 4 pixels / thread), append found points to per-tile bins.
// ---------------------------------------------------------------------------
__global__ void __launch_bounds__(256) bn_match(const float* __restrict__ src,
                                                const float* __restrict__ dst,
                                                float* __restrict__ out) {
    int q = blockIdx.x * blockDim.x + threadIdx.x;   // quad index
    if (q >= NPIX / 4) return;
    int idx = q << 2;
    int x0 = idx & (WW - 1);
    int y  = (idx / WW) % HH;
    int b  = idx / (WW * HH);
    const float* S = src + (size_t)b * HH * WW;
    const float* D = dst + (size_t)b * HH * WW;

    float4 s4 = *(const float4*)(S + y * WW + x0);
    float sv[4] = {s4.x, s4.y, s4.z, s4.w};

    float m[4]  = {0, 0, 0, 0};
    float vx[4] = {0, 0, 0, 0};
    float vy[4] = {0, 0, 0, 0};

    #pragma unroll
    for (int e = 0; e < 4; ++e) {
        if (sv[e] <= 0.5f) continue;
        int x = x0 + e;
        // sparsity: suppressed if any src pixel at a raster-preceding offset
        // within radius 2 is active.
        bool kept = true;
        for (int dy = -2; dy <= 0 && kept; ++dy) {
            int yn = y + dy;
            if (yn < 0) continue;
            int dxmax = (dy == 0) ? -1 : 2;
            for (int dx = -2; dx <= dxmax; ++dx) {
                int xn = x + dx;
                if (xn < 0 || xn >= WW) continue;
                if (__ldg(S + yn * WW + xn) > 0.5f) { kept = false; break; }
            }
        }
        if (!kept) continue;
        // ordered (distance-sorted) search: first hit wins
        for (int k = 0; k < NOFF; ++k) {
            int2 o = g_off[k];
            int X = x + o.x, Y = y + o.y;
            if (X < 0 || X >= WW || Y < 0 || Y >= HH) continue;
            if (__ldg(D + Y * WW + X) > 0.5f) {
                m[e] = 1.0f; vx[e] = (float)o.x; vy[e] = (float)o.y;
                break;
            }
        }
        if (m[e] > 0.0f) {
            int bin = (b * TY + (y >> 5)) * TX + (x >> 5);
            int pos = atomicAdd(&g_cnt[bin], 1);
            if (pos < CAP)
                g_pts[bin * CAP + pos] = make_float4((float)x, (float)y, vx[e], vy[e]);
        }
    }

    float yf = (float)y;
    float4 ox, oy, cx, cy;
    float* oxp = (float*)&ox; float* oyp = (float*)&oy;
    float* cxp = (float*)&cx; float* cyp = (float*)&cy;
    #pragma unroll
    for (int e = 0; e < 4; ++e) {
        float xf = (float)(x0 + e);
        oxp[e] = xf * m[e];
        oyp[e] = yf * m[e];
        cxp[e] = (xf + vx[e]) * m[e];
        cyp[e] = (yf + vy[e]) * m[e];
    }
    *(float4*)(out + 2 * (size_t)NPIX + idx) = ox;   // orgpts_x
    *(float4*)(out + 3 * (size_t)NPIX + idx) = oy;   // orgpts_y
    *(float4*)(out + 4 * (size_t)NPIX + idx) = cx;   // correspts_x
    *(float4*)(out + 5 * (size_t)NPIX + idx) = cy;   // correspts_y
}

// ---------------------------------------------------------------------------
// K2: sparse gather "conv". One block = one 32x32 tile, 128 threads.
//     Thread t: column (t&31), rows 8*(t>>5) .. +7 (warp = 8-row band ->
//     warp-uniform dy-band pruning). Points staged to smem first.
// ---------------------------------------------------------------------------
__global__ void __launch_bounds__(128) bn_splat(float* __restrict__ out) {
    __shared__ float sK[KSZ];
    __shared__ int   s_rx[SCAP], s_ry[SCAP];
    __shared__ float s_vx[SCAP], s_vy[SCAP];
    __shared__ int   s_cnt[9], s_bin[9], s_off[10];

    int t = threadIdx.x;
    for (int i = t; i < KSZ; i += 128) sK[i] = g_K[i];

    int blk = blockIdx.x;
    int tx = blk % TX;
    int ty = (blk / TX) % TY;
    int b  = blk / (TX * TY);
    int gx0 = tx << 5, gy0 = ty << 5;

    // gather 3x3 bin counts
    if (t < 9) {
        int nty = ty + t / 3 - 1, ntx = tx + t % 3 - 1;
        if (nty >= 0 && nty < TY && ntx >= 0 && ntx < TX) {
            int bin = (b * TY + nty) * TX + ntx;
            int c = g_cnt[bin];
            s_cnt[t] = c > CAP ? CAP : c;
            s_bin[t] = bin;
        } else { s_cnt[t] = 0; s_bin[t] = 0; }
    }
    __syncthreads();
    if (t == 0) {
        int o = 0;
        #pragma unroll
        for (int k = 0; k < 9; ++k) { s_off[k] = o; o += s_cnt[k]; }
        s_off[9] = o;
    }
    __syncthreads();
    // stage points
    #pragma unroll
    for (int k = 0; k < 9; ++k) {
        int c = s_cnt[k], base = s_off[k];
        const float4* P = g_pts + (size_t)s_bin[k] * CAP;
        for (int j = t; j < c; j += 128) {
            float4 p = P[j];
            int o = base + j;
            s_rx[o] = (int)p.x - gx0;
            s_ry[o] = (int)p.y - gy0;
            s_vx[o] = p.z;
            s_vy[o] = p.w;
        }
    }
    __syncthreads();
    int total = s_off[9];

    int lx = t & 31;
    int ybase = (t >> 5) << 3;     // 0,8,16,24 — uniform per warp

    float a0[8], a1[8], a2[8];
    #pragma unroll
    for (int i = 0; i < 8; ++i) { a0[i] = 0.f; a1[i] = 0.f; a2[i] = 0.f; }

    for (int j = 0; j < total; ++j) {
        int d0 = s_ry[j] - ybase;                 // warp-uniform
        if (d0 < -(RR + 7) || d0 > RR) continue;  // uniform branch: band prune
        int dx = s_rx[j] - lx;
        if (dx >= -RR && dx <= RR) {
            float pvx = s_vx[j], pvy = s_vy[j];
            int w0 = (d0 + RR) * KDIM + (dx + RR);
            int imax = d0 + RR;                   // dy_i = d0-i >= -RR  <=>  i <= d0+RR
            #pragma unroll
            for (int i = 0; i < 8; ++i) {
                if (i <= imax) {
                    float w = sK[w0 - i * KDIM];
                    a0[i] += w;
                    a1[i] += w * pvx;
                    a2[i] += w * pvy;
                }
            }
        }
    }

    #pragma unroll
    for (int i = 0; i < 8; ++i) {
        int gy = gy0 + ybase + i;
        size_t idx = ((size_t)b * HH + gy) * WW + gx0 + lx;
        float inv = 1.0f / (a0[i] + 1.6f);             // ALPHA_PAD
        out[idx]        = (float)(gx0 + lx) + a1[i] * inv;   // morphedx
        out[NPIX + idx] = (float)gy         + a2[i] * inv;   // morphedy
    }
}

// ---------------------------------------------------------------------------
extern "C" void kernel_launch(void* const* d_in, const int* in_sizes, int n_in,
                              void* d_out, int out_size) {
    const float* src  = (const float*)d_in[0];   // binMapsrc [8,1,320,1024]
    const float* dst  = (const float*)d_in[1];   // binMapdst
    const float* offx = (const float*)d_in[2];   // xx [105]
    const float* offy = (const float*)d_in[3];   // yy [105]
    // d_in[4], d_in[5] = sxx, syy (constant meshgrid; logic hardcoded)
    const float* cxx  = (const float*)d_in[6];   // [1681]
    const float* cyy  = (const float*)d_in[7];   // [1681]
    float* out = (float*)d_out;                  // 6 planes of [8,320,1024]

    bn_init<<<(KSZ + NBINS + 127) / 128, 128>>>(cxx, cyy, offx, offy);
    bn_match<<<(NPIX / 4 + 255) / 256, 256>>>(src, dst, out);
    bn_splat<<<NBINS, 128>>>(out);
}

// round 10
// speedup vs baseline: 1.4096x; 1.1031x over previous
#include <cuda_runtime.h>
#include <math.h>

// Problem constants (match reference hyperparameters)
#define BB 8
#define HH 320
#define WW 1024
#define NPIX (BB * HH * WW)          // 2,621,440 per plane
#define NOFF 105                      // (2*7+1)*(2*3+1) search offsets
#define RR 20                         // sense radius
#define KDIM 41
#define KSZ (KDIM * KDIM)             // 1681
#define KROWS 55                      // padded rows: dy in [-27, 27]
#define KPAD (KROWS * KDIM)           // 2255
#define TILE 32
#define TX (WW / TILE)                // 32
#define TY (HH / TILE)                // 10
#define NBINS (BB * TY * TX)          // 2560
#define CAP 256                       // >= 144 provable max points/tile
#define WCAP 512                      // provable max points in 48x96 band (spacing>=3)

// Scratch (device globals; no allocation allowed)
__device__ unsigned int g_upts[NBINS * CAP];   // packed points
__device__ int          g_cnt[NBINS];
__device__ float        g_K[KSZ];
__device__ int2         g_off[NOFF];           // packed search offsets (dx, dy)

// ---------------------------------------------------------------------------
// K0: zero bin counters, build 41x41 weight table, pack search offsets
// ---------------------------------------------------------------------------
__global__ void bn_init(const float* __restrict__ cxx, const float* __restrict__ cyy,
                        const float* __restrict__ offx, const float* __restrict__ offy) {
    int i = blockIdx.x * blockDim.x + threadIdx.x;
    if (i < NBINS) g_cnt[i] = 0;
    if (i < KSZ) {
        float cx = cxx[i], cy = cyy[i];
        float d = sqrtf(cx * cx + cy * cy);
        float w = 0.7f * expf(-d * 1.9f / 24.0f);
        g_K[((int)cy + RR) * KDIM + ((int)cx + RR)] = w;
    }
    if (i < NOFF) g_off[i] = make_int2((int)offx[i], (int)offy[i]);
}

// ---------------------------------------------------------------------------
// K1: sparsify src, ordered window match in dst, write 4 per-pixel planes
//     (4 pixels / thread, float4 I/O), append packed points to per-tile bins.
//     Point packing: x[0:10) | y[10:19) | (vx+7)[19:23) | (vy+3)[23:26)
// ---------------------------------------------------------------------------
__global__ void __launch_bounds__(256) bn_match(const float* __restrict__ src,
                                                const float* __restrict__ dst,
                                                float* __restrict__ out) {
    int q = blockIdx.x * blockDim.x + threadIdx.x;   // quad index
    if (q >= NPIX / 4) return;
    int idx = q << 2;
    int x0 = idx & (WW - 1);
    int y  = (idx / WW) % HH;
    int b  = idx / (WW * HH);
    const float* S = src + (size_t)b * HH * WW;
    const float* D = dst + (size_t)b * HH * WW;

    float4 s4 = *(const float4*)(S + y * WW + x0);
    float sv[4] = {s4.x, s4.y, s4.z, s4.w};

    float m[4]  = {0, 0, 0, 0};
    float vx[4] = {0, 0, 0, 0};
    float vy[4] = {0, 0, 0, 0};

    #pragma unroll
    for (int e = 0; e < 4; ++e) {
        if (sv[e] <= 0.5f) continue;
        int x = x0 + e;
        // sparsity: suppressed if any src pixel at a raster-preceding offset
        // within radius 2 is active.
        bool kept = true;
        for (int dy = -2; dy <= 0 && kept; ++dy) {
            int yn = y + dy;
            if (yn < 0) continue;
            int dxmax = (dy == 0) ? -1 : 2;
            for (int dx = -2; dx <= dxmax; ++dx) {
                int xn = x + dx;
                if (xn < 0 || xn >= WW) continue;
                if (__ldg(S + yn * WW + xn) > 0.5f) { kept = false; break; }
            }
        }
        if (!kept) continue;
        // ordered (distance-sorted) search: first hit wins
        int vxi = 0, vyi = 0;
        for (int k = 0; k < NOFF; ++k) {
            int2 o = g_off[k];
            int X = x + o.x, Y = y + o.y;
            if (X < 0 || X >= WW || Y < 0 || Y >= HH) continue;
            if (__ldg(D + Y * WW + X) > 0.5f) {
                m[e] = 1.0f; vxi = o.x; vyi = o.y;
                break;
            }
        }
        if (m[e] > 0.0f) {
            vx[e] = (float)vxi; vy[e] = (float)vyi;
            int bin = (b * TY + (y >> 5)) * TX + (x >> 5);
            int pos = atomicAdd(&g_cnt[bin], 1);
            if (pos < CAP) {
                unsigned int u = (unsigned int)x
                               | ((unsigned int)y << 10)
                               | ((unsigned int)(vxi + 7) << 19)
                               | ((unsigned int)(vyi + 3) << 23);
                g_upts[bin * CAP + pos] = u;
            }
        }
    }

    float yf = (float)y;
    float4 ox, oy, cx, cy;
    float* oxp = (float*)&ox; float* oyp = (float*)&oy;
    float* cxp = (float*)&cx; float* cyp = (float*)&cy;
    #pragma unroll
    for (int e = 0; e < 4; ++e) {
        float xf = (float)(x0 + e);
        oxp[e] = xf * m[e];
        oyp[e] = yf * m[e];
        cxp[e] = (xf + vx[e]) * m[e];
        cyp[e] = (yf + vy[e]) * m[e];
    }
    *(float4*)(out + 2 * (size_t)NPIX + idx) = ox;   // orgpts_x
    *(float4*)(out + 3 * (size_t)NPIX + idx) = oy;   // orgpts_y
    *(float4*)(out + 4 * (size_t)NPIX + idx) = cx;   // correspts_x
    *(float4*)(out + 5 * (size_t)NPIX + idx) = cy;   // correspts_y
}

// ---------------------------------------------------------------------------
// K2: sparse gather "conv". One block = one 32x32 tile, 128 threads.
//     Warp w covers rows 8w..8w+7, lane = column. Each warp lane-parallel
//     compacts its row-band's points (ballot) into a per-warp smem list,
//     then accumulates with a zero-padded weight table (no per-i checks).
//     Compacted packing: (rx+32)[0:8) | (ry+32)[8:16) | (vx+7)[16:20) | (vy+3)[20:23)
// ---------------------------------------------------------------------------
__global__ void __launch_bounds__(128) bn_splat(float* __restrict__ out) {
    __shared__ float        sKp[KPAD];
    __shared__ unsigned int s_list[4][WCAP];

    int t = threadIdx.x;
    // zero-padded table: rows dy in [-27,27]; real data at dy in [-20,20]
    for (int i = t; i < KPAD; i += 128) sKp[i] = 0.0f;
    __syncthreads();
    for (int i = t; i < KSZ; i += 128) sKp[i + 7 * KDIM] = g_K[i];

    int blk = blockIdx.x;
    int tx = blk % TX;
    int ty = (blk / TX) % TY;
    int b  = blk / (TX * TY);
    int gx0 = tx << 5, gy0 = ty << 5;

    int w    = t >> 5;
    int lane = t & 31;
    int ybase = w << 3;            // warp's first row within tile

    // ---- per-warp lane-parallel band compaction from the 3x3 bins ----
    int n = 0;
    #pragma unroll
    for (int k = 0; k < 9; ++k) {
        int nty = ty + k / 3 - 1, ntx = tx + k % 3 - 1;
        if (nty < 0 || nty >= TY || ntx < 0 || ntx >= TX) continue;
        int bin = (b * TY + nty) * TX + ntx;
        int cnt = __ldg(&g_cnt[bin]);
        if (cnt > CAP) cnt = CAP;
        for (int j0 = 0; j0 < cnt; j0 += 32) {
            int j = j0 + lane;
            bool valid = false;
            unsigned int pk = 0;
            if (j < cnt) {
                unsigned int u = __ldg(&g_upts[bin * CAP + j]);
                int gx = (int)(u & 1023);
                int gy = (int)((u >> 10) & 511);
                int rx = gx - gx0;
                int ry = gy - gy0;
                int d0 = ry - ybase;
                if (d0 >= -RR && d0 <= RR + 7) {      // band overlap (FIXED)
                    valid = true;
                    pk = (unsigned int)(rx + 32)
                       | ((unsigned int)(ry + 32) << 8)
                       | (((u >> 19) & 0x7Fu) << 16);
                }
            }
            unsigned int ball = __ballot_sync(0xffffffffu, valid);
            int pos = n + __popc(ball & ((1u << lane) - 1u));
            if (valid && pos < WCAP) s_list[w][pos] = pk;
            n += __popc(ball);
        }
    }
    if (n > WCAP) n = WCAP;
    __syncthreads();   // sKp center fill + own-warp list visibility

    // ---- accumulate ----
    float a0[8], a1[8], a2[8];
    #pragma unroll
    for (int i = 0; i < 8; ++i) { a0[i] = 0.f; a1[i] = 0.f; a2[i] = 0.f; }

    for (int j = 0; j < n; ++j) {
        unsigned int pk = s_list[w][j];
        int rx = (int)(pk & 255u) - 32;
        int dx = rx - lane;
        if (dx >= -RR && dx <= RR) {
            int ry = (int)((pk >> 8) & 255u) - 32;
            float vxf = (float)((int)((pk >> 16) & 15u) - 7);
            float vyf = (float)((int)((pk >> 20) & 7u) - 3);
            // row for pixel i: dy = (ry - ybase) - i, padded index dy + 27
            int base = (ry - ybase + 27) * KDIM + dx + RR;
            #pragma unroll
            for (int i = 0; i < 8; ++i) {
                float wv = sKp[base - i * KDIM];
                a0[i] += wv;
                a1[i] += wv * vxf;
                a2[i] += wv * vyf;
            }
        }
    }

    #pragma unroll
    for (int i = 0; i < 8; ++i) {
        int gy = gy0 + ybase + i;
        size_t idx = ((size_t)b * HH + gy) * WW + gx0 + lane;
        float inv = 1.0f / (a0[i] + 1.6f);                   // ALPHA_PAD
        out[idx]        = (float)(gx0 + lane) + a1[i] * inv; // morphedx
        out[NPIX + idx] = (float)gy           + a2[i] * inv; // morphedy
    }
}

// ---------------------------------------------------------------------------
extern "C" void kernel_launch(void* const* d_in, const int* in_sizes, int n_in,
                              void* d_out, int out_size) {
    const float* src  = (const float*)d_in[0];   // binMapsrc [8,1,320,1024]
    const float* dst  = (const float*)d_in[1];   // binMapdst
    const float* offx = (const float*)d_in[2];   // xx [105]
    const float* offy = (const float*)d_in[3];   // yy [105]
    // d_in[4], d_in[5] = sxx, syy (constant meshgrid; logic hardcoded)
    const float* cxx  = (const float*)d_in[6];   // [1681]
    const float* cyy  = (const float*)d_in[7];   // [1681]
    float* out = (float*)d_out;                  // 6 planes of [8,320,1024]

    bn_init<<<(KSZ + NBINS + 127) / 128, 128>>>(cxx, cyy, offx, offy);
    bn_match<<<(NPIX / 4 + 255) / 256, 256>>>(src, dst, out);
    bn_splat<<<NBINS, 128>>>(out);
}

// round 11
// speedup vs baseline: 2.3388x; 1.6591x over previous
#include <cuda_runtime.h>
#include <math.h>

// Problem constants (match reference hyperparameters)
#define BB 8
#define HH 320
#define WW 1024
#define NPIX (BB * HH * WW)          // 2,621,440 per plane
#define NOFF 105                      // (2*7+1)*(2*3+1) search offsets
#define RR 20                         // sense radius
#define KDIM 41
#define KROWS 55                      // padded rows: dy in [-27, 27]
#define KPAD (KROWS * KDIM)           // 2255
#define TX 32                         // tiles in x (1024/32)
#define TY 10                         // tiles in y (320/32)
#define NBINS (BB * TY * TX)          // 2560
#define CAP 256                       // >= 144 provable max points/tile
#define WCAP 512                      // provable max per warp band list
#define WPR 32                        // mask words per row (1024/32)
#define MWORDS (BB * HH * WPR)        // 81920 words per map

// Scratch (device globals; no allocation allowed)
__device__ unsigned int  g_msrc[MWORDS];       // src bitmask
__device__ unsigned int  g_mdst[MWORDS];       // dst bitmask
__device__ unsigned int  g_upts[NBINS * CAP];  // packed points
__device__ int           g_cnt[NBINS];
__device__ float         g_Kpad[KPAD];         // pre-padded weight table
__device__ int2          g_voff[NOFF];         // offsets by rank (search order)
__device__ unsigned char g_rank[NOFF];         // window bit pos -> rank

#define MASK_BLOCKS (2 * MWORDS / 8)  // 8 warps/block -> 20480 blocks
#define TAB_BLOCKS  12

// ---------------------------------------------------------------------------
// K0: build bitmasks of src/dst (ballot), zero bins, build padded table,
//     build rank/offset tables.
// ---------------------------------------------------------------------------
__global__ void __launch_bounds__(256) bn_init(const float* __restrict__ src,
                                               const float* __restrict__ dst,
                                               const float* __restrict__ offx,
                                               const float* __restrict__ offy) {
    if (blockIdx.x < MASK_BLOCKS) {
        int gw = blockIdx.x * 8 + (threadIdx.x >> 5);
        int lane = threadIdx.x & 31;
        const float* p; unsigned* q; int w = gw;
        if (w < MWORDS) { p = src; q = g_msrc; }
        else            { w -= MWORDS; p = dst; q = g_mdst; }
        float v = p[(size_t)w * 32 + lane];
        unsigned b = __ballot_sync(0xffffffffu, v > 0.5f);
        if (lane == 0) q[w] = b;
        return;
    }
    int i = (blockIdx.x - MASK_BLOCKS) * 256 + threadIdx.x;
    if (i < NBINS) g_cnt[i] = 0;
    if (i < KPAD) {
        int row = i / KDIM, col = i - row * KDIM;
        int dy = row - 27, dx = col - RR;
        float w = 0.0f;
        if (dy >= -RR && dy <= RR) {
            float d = sqrtf((float)(dx * dx + dy * dy));
            w = 0.7f * expf(-d * 1.9f / 24.0f);
        }
        g_Kpad[i] = w;
    }
    if (i < NOFF) {
        int ox = (int)offx[i], oy = (int)offy[i];
        g_voff[i] = make_int2(ox, oy);
        g_rank[(oy + 3) * 15 + (ox + 7)] = (unsigned char)i;
    }
}

// ---------------------------------------------------------------------------
// extract 32 bits starting at column c0 of a mask row (0 outside [0,1024))
// ---------------------------------------------------------------------------
__device__ __forceinline__ unsigned ex32(const unsigned* __restrict__ row, int c0) {
    int w0 = c0 >> 5;            // arithmetic shift: -1 for negative c0
    int sh = c0 & 31;
    unsigned a = ((unsigned)w0 < WPR) ? __ldg(row + w0) : 0u;
    unsigned b = ((unsigned)(w0 + 1) < WPR) ? __ldg(row + w0 + 1) : 0u;
    return __funnelshift_r(a, b, sh);
}

// ---------------------------------------------------------------------------
// K1: mask-based sparsify + ordered search (set-bit iteration with rank min),
//     write 4 per-pixel planes (4 px/thread float4), append packed points.
//     Point packing: x[0:10) | y[10:19) | (vx+7)[19:23) | (vy+3)[23:26)
// ---------------------------------------------------------------------------
__global__ void __launch_bounds__(256) bn_match(float* __restrict__ out) {
    __shared__ unsigned char s_rank[NOFF];
    __shared__ int2          s_off[NOFF];
    int t = threadIdx.x;
    if (t < NOFF) { s_rank[t] = g_rank[t]; s_off[t] = g_voff[t]; }
    __syncthreads();

    int q = blockIdx.x * 256 + t;            // quad index
    int idx = q << 2;
    int x0 = idx & (WW - 1);
    int y  = (idx / WW) % HH;
    int b  = idx / (WW * HH);

    const unsigned* MS = g_msrc + (size_t)b * HH * WPR;
    const unsigned* MD = g_mdst + (size_t)b * HH * WPR;

    unsigned own = __ldg(MS + y * WPR + (x0 >> 5));
    unsigned bits4 = (own >> (x0 & 31)) & 15u;

    float m[4]  = {0, 0, 0, 0};
    float vx[4] = {0, 0, 0, 0};
    float vy[4] = {0, 0, 0, 0};

    if (bits4) {
        // sparsity rows (shared across the quad): window starts at x0-2
        int c0s = x0 - 2;
        unsigned rA = (y >= 2) ? ex32(MS + (y - 2) * WPR, c0s) : 0u;
        unsigned rB = (y >= 1) ? ex32(MS + (y - 1) * WPR, c0s) : 0u;
        unsigned rC = ex32(MS + y * WPR, c0s);
        // dst window rows (shared across the quad): start at x0-7
        int c0 = x0 - 7;
        unsigned r[7];
        #pragma unroll
        for (int j = 0; j < 7; ++j) {
            int Y = y + j - 3;
            r[j] = (Y >= 0 && Y < HH) ? ex32(MD + Y * WPR, c0) : 0u;
        }
        #pragma unroll
        for (int e = 0; e < 4; ++e) {
            if (!((bits4 >> e) & 1u)) continue;
            // raster-preceding neighbors within radius 2
            unsigned blocked = ((rA >> e) & 31u) | ((rB >> e) & 31u) | ((rC >> e) & 3u);
            if (blocked) continue;
            // build 105-bit window (7 rows x 15 bits), bit G = row*15 + col
            unsigned long long lo, hi;
            {
                unsigned w0_ = (r[0] >> e) & 0x7FFFu, w1_ = (r[1] >> e) & 0x7FFFu,
                         w2_ = (r[2] >> e) & 0x7FFFu, w3_ = (r[3] >> e) & 0x7FFFu,
                         w4_ = (r[4] >> e) & 0x7FFFu, w5_ = (r[5] >> e) & 0x7FFFu,
                         w6_ = (r[6] >> e) & 0x7FFFu;
                lo = (unsigned long long)w0_
                   | ((unsigned long long)w1_ << 15)
                   | ((unsigned long long)w2_ << 30)
                   | ((unsigned long long)w3_ << 45)
                   | ((unsigned long long)(w4_ & 0xFu) << 60);
                hi = (unsigned long long)(w4_ >> 4)
                   | ((unsigned long long)w5_ << 11)
                   | ((unsigned long long)w6_ << 26);
            }
            // nearest hit = min rank over set bits
            int rmin = 255;
            unsigned long long mm = lo;
            while (mm) {
                int g = __ffsll(mm) - 1; mm &= mm - 1;
                int rk = s_rank[g]; rmin = rk < rmin ? rk : rmin;
            }
            mm = hi;
            while (mm) {
                int g = __ffsll(mm) - 1; mm &= mm - 1;
                int rk = s_rank[64 + g]; rmin = rk < rmin ? rk : rmin;
            }
            if (rmin < 255) {
                int2 o = s_off[rmin];
                m[e] = 1.0f; vx[e] = (float)o.x; vy[e] = (float)o.y;
                int x = x0 + e;
                int bin = (b * TY + (y >> 5)) * TX + (x >> 5);
                int pos = atomicAdd(&g_cnt[bin], 1);
                if (pos < CAP) {
                    g_upts[bin * CAP + pos] = (unsigned)x
                        | ((unsigned)y << 10)
                        | ((unsigned)(o.x + 7) << 19)
                        | ((unsigned)(o.y + 3) << 23);
                }
            }
        }
    }

    float yf = (float)y;
    float4 ox, oy, cx, cy;
    float* oxp = (float*)&ox; float* oyp = (float*)&oy;
    float* cxp = (float*)&cx; float* cyp = (float*)&cy;
    #pragma unroll
    for (int e = 0; e < 4; ++e) {
        float xf = (float)(x0 + e);
        oxp[e] = xf * m[e];
        oyp[e] = yf * m[e];
        cxp[e] = (xf + vx[e]) * m[e];
        cyp[e] = (yf + vy[e]) * m[e];
    }
    *(float4*)(out + 2 * (size_t)NPIX + idx) = ox;   // orgpts_x
    *(float4*)(out + 3 * (size_t)NPIX + idx) = oy;   // orgpts_y
    *(float4*)(out + 4 * (size_t)NPIX + idx) = cx;   // correspts_x
    *(float4*)(out + 5 * (size_t)NPIX + idx) = cy;   // correspts_y
}

// ---------------------------------------------------------------------------
// K2: sparse gather "conv". One block = one 32x32 tile, 128 threads.
//     Warp w: rows 8w..8w+7, lane = column. Lane-parallel band+x compaction
//     (ballot) into per-warp smem list; accumulate with pre-padded table.
//     Compacted: (rx+32)[0:8) | (ry+32)[8:16) | (vx+7)[16:20) | (vy+3)[20:23)
// ---------------------------------------------------------------------------
__global__ void __launch_bounds__(128) bn_splat(float* __restrict__ out) {
    __shared__ float        sKp[KPAD];
    __shared__ unsigned int s_list[4][WCAP];

    int t = threadIdx.x;
    for (int i = t; i < KPAD; i += 128) sKp[i] = g_Kpad[i];

    int blk = blockIdx.x;
    int tx = blk % TX;
    int ty = (blk / TX) % TY;
    int b  = blk / (TX * TY);
    int gx0 = tx << 5, gy0 = ty << 5;

    int w    = t >> 5;
    int lane = t & 31;
    int ybase = w << 3;            // warp's first row within tile

    // prefetch the 9 bin counts lane-parallel (kills serialized L2 chain)
    int cnt_l = 0, bin_l = 0;
    if (lane < 9) {
        int nty = ty + lane / 3 - 1, ntx = tx + lane % 3 - 1;
        if (nty >= 0 && nty < TY && ntx >= 0 && ntx < TX) {
            bin_l = (b * TY + nty) * TX + ntx;
            int c = __ldg(&g_cnt[bin_l]);
            cnt_l = c > CAP ? CAP : c;
        }
    }

    // ---- per-warp lane-parallel band + x compaction ----
    int n = 0;
    #pragma unroll
    for (int k = 0; k < 9; ++k) {
        int cnt = __shfl_sync(0xffffffffu, cnt_l, k);
        int bin = __shfl_sync(0xffffffffu, bin_l, k);
        for (int j0 = 0; j0 < cnt; j0 += 32) {
            int j = j0 + lane;
            bool valid = false;
            unsigned pk = 0;
            if (j < cnt) {
                unsigned u = __ldg(&g_upts[bin * CAP + j]);
                int rx = (int)(u & 1023u) - gx0;
                int ry = (int)((u >> 10) & 511u) - gy0;
                int d0 = ry - ybase;
                if (d0 >= -RR && d0 <= RR + 7 && rx >= -RR && rx <= 31 + RR) {
                    valid = true;
                    pk = (unsigned)(rx + 32)
                       | ((unsigned)(ry + 32) << 8)
                       | (((u >> 19) & 0x7Fu) << 16);
                }
            }
            unsigned ball = __ballot_sync(0xffffffffu, valid);
            int pos = n + __popc(ball & ((1u << lane) - 1u));
            if (valid && pos < WCAP) s_list[w][pos] = pk;
            n += __popc(ball);
        }
    }
    if (n > WCAP) n = WCAP;
    __syncthreads();   // sKp ready + own-warp list visibility

    // ---- accumulate ----
    float a0[8], a1[8], a2[8];
    #pragma unroll
    for (int i = 0; i < 8; ++i) { a0[i] = 0.f; a1[i] = 0.f; a2[i] = 0.f; }

    for (int j = 0; j < n; ++j) {
        unsigned pk = s_list[w][j];
        int rx = (int)(pk & 255u) - 32;
        int dx = rx - lane;
        if ((unsigned)(dx + RR) <= 2u * RR) {
            int ry = (int)((pk >> 8) & 255u) - 32;
            float vxf = (float)((int)((pk >> 16) & 15u) - 7);
            float vyf = (float)((int)((pk >> 20) & 7u) - 3);
            // row for pixel i: dy = (ry - ybase) - i, padded index dy + 27
            int base = (ry - ybase + 27) * KDIM + dx + RR;
            #pragma unroll
            for (int i = 0; i < 8; ++i) {
                float wv = sKp[base - i * KDIM];
                a0[i] += wv;
                a1[i] += wv * vxf;
                a2[i] += wv * vyf;
            }
        }
    }

    #pragma unroll
    for (int i = 0; i < 8; ++i) {
        int gy = gy0 + ybase + i;
        size_t idx = ((size_t)b * HH + gy) * WW + gx0 + lane;
        float inv = 1.0f / (a0[i] + 1.6f);                    // ALPHA_PAD
        out[idx]        = (float)(gx0 + lane) + a1[i] * inv;  // morphedx
        out[NPIX + idx] = (float)gy           + a2[i] * inv;  // morphedy
    }
}

// ---------------------------------------------------------------------------
extern "C" void kernel_launch(void* const* d_in, const int* in_sizes, int n_in,
                              void* d_out, int out_size) {
    const float* src  = (const float*)d_in[0];   // binMapsrc [8,1,320,1024]
    const float* dst  = (const float*)d_in[1];   // binMapdst
    const float* offx = (const float*)d_in[2];   // xx [105]
    const float* offy = (const float*)d_in[3];   // yy [105]
    // d_in[4..7] = sxx, syy, cxx, cyy (constant grids; recomputed in closed form)
    float* out = (float*)d_out;                  // 6 planes of [8,320,1024]

    bn_init<<<MASK_BLOCKS + TAB_BLOCKS, 256>>>(src, dst, offx, offy);
    bn_match<<<(NPIX / 4) / 256, 256>>>(out);
    bn_splat<<<NBINS, 128>>>(out);
}

// round 12
// speedup vs baseline: 2.5110x; 1.0736x over previous
#include <cuda_runtime.h>
#include <math.h>

// Problem constants (match reference hyperparameters)
#define BB 8
#define HH 320
#define WW 1024
#define NPIX (BB * HH * WW)          // 2,621,440 per plane
#define NOFF 105                      // (2*7+1)*(2*3+1) search offsets
#define RR 20                         // sense radius
#define KDIM 41
#define KROWS 55                      // padded rows: dy in [-27, 27]
#define KPAD (KROWS * KDIM)           // 2255
#define TX 32                         // tiles in x (1024/32)
#define TY 10                         // tiles in y (320/32)
#define NBINS (BB * TY * TX)          // 2560
#define CAP 256                       // >= 144 provable max points/tile
#define WCAP 512                      // provable max per warp band list
#define WPR 32                        // mask words per row (1024/32)
#define MWORDS (BB * HH * WPR)        // 81920 words per map

// Scratch (device globals; no allocation allowed)
__device__ unsigned int  g_msrc[MWORDS];       // src bitmask
__device__ unsigned int  g_mdst[MWORDS];       // dst bitmask
__device__ unsigned int  g_upts[NBINS * CAP];  // packed points
__device__ int           g_cnt[NBINS];
__device__ float         g_Kpad[KPAD];         // pre-padded weight table
__device__ int2          g_voff[NOFF];         // offsets by rank (search order)
__device__ unsigned char g_rank[NOFF];         // window bit pos -> rank

#define NOCT (2 * NPIX / 8)           // pixel-octets across both maps: 655360
#define MASK_BLOCKS (NOCT / 256)      // 2560
#define TAB_BLOCKS  12

// ---------------------------------------------------------------------------
// K0: build bitmasks (8 px/thread: float4 x2 -> nibble -> shfl-or), zero bins,
//     build padded table + rank/offset tables.
// ---------------------------------------------------------------------------
__global__ void __launch_bounds__(256) bn_init(const float* __restrict__ src,
                                               const float* __restrict__ dst,
                                               const float* __restrict__ offx,
                                               const float* __restrict__ offy) {
    if (blockIdx.x < MASK_BLOCKS) {
        int gid = blockIdx.x * 256 + threadIdx.x;   // octet id
        int lane = threadIdx.x & 31;
        const float* p; unsigned* q; int o = gid;
        if (o < NPIX / 8) { p = src; q = g_msrc; }
        else              { o -= NPIX / 8; p = dst; q = g_mdst; }
        float4 v0 = ((const float4*)p)[(size_t)o * 2];
        float4 v1 = ((const float4*)p)[(size_t)o * 2 + 1];
        unsigned nib =  (v0.x > 0.5f ? 1u : 0u)  | (v0.y > 0.5f ? 2u : 0u)
                     |  (v0.z > 0.5f ? 4u : 0u)  | (v0.w > 0.5f ? 8u : 0u)
                     |  (v1.x > 0.5f ? 16u : 0u) | (v1.y > 0.5f ? 32u : 0u)
                     |  (v1.z > 0.5f ? 64u : 0u) | (v1.w > 0.5f ? 128u : 0u);
        unsigned val = nib << (8 * (lane & 3));
        val |= __shfl_xor_sync(0xffffffffu, val, 1);
        val |= __shfl_xor_sync(0xffffffffu, val, 2);
        if ((lane & 3) == 0) q[o >> 2] = val;
        return;
    }
    int i = (blockIdx.x - MASK_BLOCKS) * 256 + threadIdx.x;
    if (i < NBINS) g_cnt[i] = 0;
    if (i < KPAD) {
        int row = i / KDIM, col = i - row * KDIM;
        int dy = row - 27, dx = col - RR;
        float w = 0.0f;
        if (dy >= -RR && dy <= RR) {
            float d = sqrtf((float)(dx * dx + dy * dy));
            w = 0.7f * expf(-d * 1.9f / 24.0f);
        }
        g_Kpad[i] = w;
    }
    if (i < NOFF) {
        int ox = (int)offx[i], oy = (int)offy[i];
        g_voff[i] = make_int2(ox, oy);
        g_rank[(oy + 3) * 15 + (ox + 7)] = (unsigned char)i;
    }
}

// ---------------------------------------------------------------------------
// extract 32 bits starting at column c0 of a mask row (0 outside [0,1024))
// ---------------------------------------------------------------------------
__device__ __forceinline__ unsigned ex32(const unsigned* __restrict__ row, int c0) {
    int w0 = c0 >> 5;            // arithmetic shift: -1 for negative c0
    int sh = c0 & 31;
    unsigned a = ((unsigned)w0 < WPR) ? __ldg(row + w0) : 0u;
    unsigned b = ((unsigned)(w0 + 1) < WPR) ? __ldg(row + w0 + 1) : 0u;
    return __funnelshift_r(a, b, sh);
}

// ---------------------------------------------------------------------------
// K1: mask-based sparsify + ordered search (set-bit iteration with rank min),
//     write 4 per-pixel planes (4 px/thread float4), append packed points.
//     Point packing: x[0:10) | y[10:19) | (vx+7)[19:23) | (vy+3)[23:26)
// ---------------------------------------------------------------------------
__global__ void __launch_bounds__(256) bn_match(float* __restrict__ out) {
    __shared__ unsigned char s_rank[NOFF];
    __shared__ int2          s_off[NOFF];
    int t = threadIdx.x;
    if (t < NOFF) { s_rank[t] = g_rank[t]; s_off[t] = g_voff[t]; }
    __syncthreads();

    int q = blockIdx.x * 256 + t;            // quad index
    int idx = q << 2;
    int x0 = idx & (WW - 1);
    int y  = (idx / WW) % HH;
    int b  = idx / (WW * HH);

    const unsigned* MS = g_msrc + (size_t)b * HH * WPR;
    const unsigned* MD = g_mdst + (size_t)b * HH * WPR;

    unsigned own = __ldg(MS + y * WPR + (x0 >> 5));
    unsigned bits4 = (own >> (x0 & 31)) & 15u;

    float m[4]  = {0, 0, 0, 0};
    float vx[4] = {0, 0, 0, 0};
    float vy[4] = {0, 0, 0, 0};

    if (bits4) {
        // sparsity rows (shared across the quad): window starts at x0-2
        int c0s = x0 - 2;
        unsigned rA = (y >= 2) ? ex32(MS + (y - 2) * WPR, c0s) : 0u;
        unsigned rB = (y >= 1) ? ex32(MS + (y - 1) * WPR, c0s) : 0u;
        unsigned rC = ex32(MS + y * WPR, c0s);
        // dst window rows (shared across the quad): start at x0-7
        int c0 = x0 - 7;
        unsigned r[7];
        #pragma unroll
        for (int j = 0; j < 7; ++j) {
            int Y = y + j - 3;
            r[j] = (Y >= 0 && Y < HH) ? ex32(MD + Y * WPR, c0) : 0u;
        }
        #pragma unroll
        for (int e = 0; e < 4; ++e) {
            if (!((bits4 >> e) & 1u)) continue;
            // raster-preceding neighbors within radius 2
            unsigned blocked = ((rA >> e) & 31u) | ((rB >> e) & 31u) | ((rC >> e) & 3u);
            if (blocked) continue;
            // build 105-bit window (7 rows x 15 bits), bit G = row*15 + col
            unsigned long long lo, hi;
            {
                unsigned w0_ = (r[0] >> e) & 0x7FFFu, w1_ = (r[1] >> e) & 0x7FFFu,
                         w2_ = (r[2] >> e) & 0x7FFFu, w3_ = (r[3] >> e) & 0x7FFFu,
                         w4_ = (r[4] >> e) & 0x7FFFu, w5_ = (r[5] >> e) & 0x7FFFu,
                         w6_ = (r[6] >> e) & 0x7FFFu;
                lo = (unsigned long long)w0_
                   | ((unsigned long long)w1_ << 15)
                   | ((unsigned long long)w2_ << 30)
                   | ((unsigned long long)w3_ << 45)
                   | ((unsigned long long)(w4_ & 0xFu) << 60);
                hi = (unsigned long long)(w4_ >> 4)
                   | ((unsigned long long)w5_ << 11)
                   | ((unsigned long long)w6_ << 26);
            }
            // nearest hit = min rank over set bits
            int rmin = 255;
            unsigned long long mm = lo;
            while (mm) {
                int g = __ffsll(mm) - 1; mm &= mm - 1;
                int rk = s_rank[g]; rmin = rk < rmin ? rk : rmin;
            }
            mm = hi;
            while (mm) {
                int g = __ffsll(mm) - 1; mm &= mm - 1;
                int rk = s_rank[64 + g]; rmin = rk < rmin ? rk : rmin;
            }
            if (rmin < 255) {
                int2 o = s_off[rmin];
                m[e] = 1.0f; vx[e] = (float)o.x; vy[e] = (float)o.y;
                int x = x0 + e;
                int bin = (b * TY + (y >> 5)) * TX + (x >> 5);
                int pos = atomicAdd(&g_cnt[bin], 1);
                if (pos < CAP) {
                    g_upts[bin * CAP + pos] = (unsigned)x
                        | ((unsigned)y << 10)
                        | ((unsigned)(o.x + 7) << 19)
                        | ((unsigned)(o.y + 3) << 23);
                }
            }
        }
    }

    float yf = (float)y;
    float4 ox, oy, cx, cy;
    float* oxp = (float*)&ox; float* oyp = (float*)&oy;
    float* cxp = (float*)&cx; float* cyp = (float*)&cy;
    #pragma unroll
    for (int e = 0; e < 4; ++e) {
        float xf = (float)(x0 + e);
        oxp[e] = xf * m[e];
        oyp[e] = yf * m[e];
        cxp[e] = (xf + vx[e]) * m[e];
        cyp[e] = (yf + vy[e]) * m[e];
    }
    *(float4*)(out + 2 * (size_t)NPIX + idx) = ox;   // orgpts_x
    *(float4*)(out + 3 * (size_t)NPIX + idx) = oy;   // orgpts_y
    *(float4*)(out + 4 * (size_t)NPIX + idx) = cx;   // correspts_x
    *(float4*)(out + 5 * (size_t)NPIX + idx) = cy;   // correspts_y
}

// ---------------------------------------------------------------------------
// K2: sparse gather "conv". One block = one 32x32 tile, 128 threads.
//     Warp w: rows 8w..8w+7, lane = column. Lane-parallel band+x compaction
//     (ballot) into per-warp smem list. Accumulate uses a DUPLICATED-PAIR
//     weight table (w,w) so each row-step is LDS.64 + add.f32x2 + fma.f32x2.
//     Compacted: (rx+32)[0:8) | (ry+32)[8:16) | (vx+7)[16:20) | (vy+3)[20:23)
// ---------------------------------------------------------------------------
__global__ void __launch_bounds__(128) bn_splat(float* __restrict__ out) {
    __shared__ unsigned long long sKd[KPAD];   // (w, w) packed pairs
    __shared__ unsigned int s_list[4][WCAP];

    int t = threadIdx.x;
    for (int i = t; i < KPAD; i += 128) {
        unsigned wu = __float_as_uint(g_Kpad[i]);
        unsigned long long wp;
        asm("mov.b64 %0, {%1, %1};" : "=l"(wp) : "r"(wu));
        sKd[i] = wp;
    }

    int blk = blockIdx.x;
    int tx = blk % TX;
    int ty = (blk / TX) % TY;
    int b  = blk / (TX * TY);
    int gx0 = tx << 5, gy0 = ty << 5;

    int w    = t >> 5;
    int lane = t & 31;
    int ybase = w << 3;            // warp's first row within tile

    // prefetch the 9 bin counts lane-parallel (kills serialized L2 chain)
    int cnt_l = 0, bin_l = 0;
    if (lane < 9) {
        int nty = ty + lane / 3 - 1, ntx = tx + lane % 3 - 1;
        if (nty >= 0 && nty < TY && ntx >= 0 && ntx < TX) {
            bin_l = (b * TY + nty) * TX + ntx;
            int c = __ldg(&g_cnt[bin_l]);
            cnt_l = c > CAP ? CAP : c;
        }
    }

    // ---- per-warp lane-parallel band + x compaction ----
    int n = 0;
    #pragma unroll
    for (int k = 0; k < 9; ++k) {
        int cnt = __shfl_sync(0xffffffffu, cnt_l, k);
        int bin = __shfl_sync(0xffffffffu, bin_l, k);
        for (int j0 = 0; j0 < cnt; j0 += 32) {
            int j = j0 + lane;
            bool valid = false;
            unsigned pk = 0;
            if (j < cnt) {
                unsigned u = __ldg(&g_upts[bin * CAP + j]);
                int rx = (int)(u & 1023u) - gx0;
                int ry = (int)((u >> 10) & 511u) - gy0;
                int d0 = ry - ybase;
                if (d0 >= -RR && d0 <= RR + 7 && rx >= -RR && rx <= 31 + RR) {
                    valid = true;
                    pk = (unsigned)(rx + 32)
                       | ((unsigned)(ry + 32) << 8)
                       | (((u >> 19) & 0x7Fu) << 16);
                }
            }
            unsigned ball = __ballot_sync(0xffffffffu, valid);
            int pos = n + __popc(ball & ((1u << lane) - 1u));
            if (valid && pos < WCAP) s_list[w][pos] = pk;
            n += __popc(ball);
        }
    }
    if (n > WCAP) n = WCAP;
    __syncthreads();   // sKd ready + own-warp list visibility

    // ---- accumulate (packed f32x2) ----
    unsigned long long A0[8], A12[8];   // A0 = (a0, a0); A12 = (a1, a2)
    #pragma unroll
    for (int i = 0; i < 8; ++i) { A0[i] = 0ull; A12[i] = 0ull; }

    for (int j = 0; j < n; ++j) {
        unsigned pk = s_list[w][j];
        int rx = (int)(pk & 255u) - 32;
        int dx = rx - lane;
        if ((unsigned)(dx + RR) <= 2u * RR) {
            int ry = (int)((pk >> 8) & 255u) - 32;
            unsigned vxu = __float_as_uint((float)((int)((pk >> 16) & 15u) - 7));
            unsigned vyu = __float_as_uint((float)((int)((pk >> 20) & 7u) - 3));
            unsigned long long vxy;
            asm("mov.b64 %0, {%1, %2};" : "=l"(vxy) : "r"(vxu), "r"(vyu));
            // row for pixel i: dy = (ry - ybase) - i, padded index dy + 27
            int base = (ry - ybase + 27) * KDIM + dx + RR;
            #pragma unroll
            for (int i = 0; i < 8; ++i) {
                unsigned long long wp = sKd[base - i * KDIM];
                asm("add.rn.f32x2 %0, %0, %1;" : "+l"(A0[i]) : "l"(wp));
                asm("fma.rn.f32x2 %0, %1, %2, %0;" : "+l"(A12[i]) : "l"(wp), "l"(vxy));
            }
        }
    }

    #pragma unroll
    for (int i = 0; i < 8; ++i) {
        unsigned a0u, dummy, a1u, a2u;
        asm("mov.b64 {%0, %1}, %2;" : "=r"(a0u), "=r"(dummy) : "l"(A0[i]));
        asm("mov.b64 {%0, %1}, %2;" : "=r"(a1u), "=r"(a2u) : "l"(A12[i]));
        int gy = gy0 + ybase + i;
        size_t idx = ((size_t)b * HH + gy) * WW + gx0 + lane;
        float inv = 1.0f / (__uint_as_float(a0u) + 1.6f);    // ALPHA_PAD
        out[idx]        = (float)(gx0 + lane) + __uint_as_float(a1u) * inv; // morphedx
        out[NPIX + idx] = (float)gy           + __uint_as_float(a2u) * inv; // morphedy
    }
}

// ---------------------------------------------------------------------------
extern "C" void kernel_launch(void* const* d_in, const int* in_sizes, int n_in,
                              void* d_out, int out_size) {
    const float* src  = (const float*)d_in[0];   // binMapsrc [8,1,320,1024]
    const float* dst  = (const float*)d_in[1];   // binMapdst
    const float* offx = (const float*)d_in[2];   // xx [105]
    const float* offy = (const float*)d_in[3];   // yy [105]
    // d_in[4..7] = sxx, syy, cxx, cyy (constant grids; recomputed in closed form)
    float* out = (float*)d_out;                  // 6 planes of [8,320,1024]

    bn_init<<<MASK_BLOCKS + TAB_BLOCKS, 256>>>(src, dst, offx, offy);
    bn_match<<<(NPIX / 4) / 256, 256>>>(out);
    bn_splat<<<NBINS, 128>>>(out);
}